// round 5
// baseline (speedup 1.0000x reference)
#include <cuda_runtime.h>
#include <cuda_bf16.h>
#include <math.h>
#include <stdint.h>

// Problem constants
#define BATCH 32
#define TT 64
#define SS 64
#define VV 32000
#define EE 512
#define HH 512
#define NCTA 144

// ---------------- device scratch (no cudaMalloc allowed) ----------------
__device__ float g_embT[TT * BATCH * EE];        // [t][b][e]
__device__ float g_h[2 * BATCH * HH];            // [l][b][h]
__device__ float g_c[2 * BATCH * HH];
__device__ float g_feat[TT * BATCH * 1024];      // [t][b][ h1(512) | ctx(512) ]
__device__ float g_gpart[12 * BATCH * 2048];     // recurrence partial buffers
__device__ float g_qpart[4 * BATCH * HH];        // q buffer
__device__ float g_embpre[TT * BATCH * 2048];    // precomputed emb @ Wih0[:, :512]^T
__device__ unsigned g_barcnt;                    // grid barrier counter
// bf16 split operands for tensor-core projection GEMM
__device__ __nv_bfloat16 g_WH[VV * 1024];
__device__ __nv_bfloat16 g_WL[VV * 1024];
__device__ __nv_bfloat16 g_fH[2048 * 1024];
__device__ __nv_bfloat16 g_fL[2048 * 1024];

// ---------------- PTX helpers (sm_80-tier: plain compute_103 target) -------
__device__ __forceinline__ uint32_t smem_to_u32(const void* p) {
    uint32_t a;
    asm("{ .reg .u64 t; cvta.to.shared.u64 t, %1; cvt.u32.u64 %0, t; }" : "=r"(a) : "l"(p));
    return a;
}
#define CP16(dst, src) \
    asm volatile("cp.async.cg.shared.global [%0], [%1], 16;" \
                 :: "r"(dst), "l"(src) : "memory")
#define CP_COMMIT() asm volatile("cp.async.commit_group;" ::: "memory")
#define CP_WAIT0()  asm volatile("cp.async.wait_group 0;" ::: "memory")
#define CP_WAIT1()  asm volatile("cp.async.wait_group 1;" ::: "memory")

#define LDSM_X4(r0, r1, r2, r3, addr) \
    asm volatile("ldmatrix.sync.aligned.m8n8.x4.shared.b16 {%0,%1,%2,%3}, [%4];" \
                 : "=r"(r0), "=r"(r1), "=r"(r2), "=r"(r3) : "r"(addr))
#define LDSM_X2(r0, r1, addr) \
    asm volatile("ldmatrix.sync.aligned.m8n8.x2.shared.b16 {%0,%1}, [%2];" \
                 : "=r"(r0), "=r"(r1) : "r"(addr))

#define MMA_BF16(c, a0, a1, a2, a3, b0, b1) \
    asm volatile("mma.sync.aligned.m16n8k16.row.col.f32.bf16.bf16.f32 " \
                 "{%0,%1,%2,%3}, {%4,%5,%6,%7}, {%8,%9}, {%0,%1,%2,%3};" \
                 : "+f"((c)[0]), "+f"((c)[1]), "+f"((c)[2]), "+f"((c)[3]) \
                 : "r"(a0), "r"(a1), "r"(a2), "r"(a3), "r"(b0), "r"(b1))

// ---------------- utility kernels ----------------
__global__ void init_state_kernel(const float* __restrict__ hidden,
                                  const float* __restrict__ cell) {
    int i = blockIdx.x * blockDim.x + threadIdx.x;
    if (i == 0) g_barcnt = 0u;
    if (i < 2 * BATCH * HH) { g_h[i] = hidden[i]; g_c[i] = cell[i]; }
}

__global__ void tail_copy_kernel(float* __restrict__ out) {
    int i = blockIdx.x * blockDim.x + threadIdx.x;
    const long long OFF = (long long)BATCH * TT * VV;
    if (i < 2 * BATCH * HH) {
        out[OFF + i] = g_h[i];
        out[OFF + 2 * BATCH * HH + i] = g_c[i];
    }
}

__global__ void embed_kernel(const int* __restrict__ tgt,
                             const float* __restrict__ emb) {
    int blk = blockIdx.x;             // b*TT + t
    int b = blk >> 6, t = blk & 63;
    int idx = tgt[blk];
    const float4* src = reinterpret_cast<const float4*>(emb + (long long)idx * EE);
    float4* dst = reinterpret_cast<float4*>(g_embT + ((long long)t * BATCH + b) * EE);
    float4 v;
    if (idx == 0) { v.x = v.y = v.z = v.w = 0.f; }
    else          { v = src[threadIdx.x]; }
    dst[threadIdx.x] = v;
}

// split fp32 -> bf16 hi + bf16 lo (residual)
__global__ void split_bf16_kernel(const float4* __restrict__ in,
                                  uint2* __restrict__ hi, uint2* __restrict__ lo, int n4) {
    for (int i = blockIdx.x * blockDim.x + threadIdx.x; i < n4; i += gridDim.x * blockDim.x) {
        float4 x = in[i];
        __nv_bfloat16 h0 = __float2bfloat16(x.x), h1 = __float2bfloat16(x.y);
        __nv_bfloat16 h2 = __float2bfloat16(x.z), h3 = __float2bfloat16(x.w);
        __nv_bfloat16 l0 = __float2bfloat16(x.x - __bfloat162float(h0));
        __nv_bfloat16 l1 = __float2bfloat16(x.y - __bfloat162float(h1));
        __nv_bfloat16 l2 = __float2bfloat16(x.z - __bfloat162float(h2));
        __nv_bfloat16 l3 = __float2bfloat16(x.w - __bfloat162float(h3));
        uint2 hv, lv;
        hv.x = (uint32_t)__bfloat16_as_ushort(h0) | ((uint32_t)__bfloat16_as_ushort(h1) << 16);
        hv.y = (uint32_t)__bfloat16_as_ushort(h2) | ((uint32_t)__bfloat16_as_ushort(h3) << 16);
        lv.x = (uint32_t)__bfloat16_as_ushort(l0) | ((uint32_t)__bfloat16_as_ushort(l1) << 16);
        lv.y = (uint32_t)__bfloat16_as_ushort(l2) | ((uint32_t)__bfloat16_as_ushort(l3) << 16);
        hi[i] = hv; lo[i] = lv;
    }
}

// ---------------- embpre: [2048,2048] = embT[2048,512] @ Wih0[:, :512]^T ----
__global__ __launch_bounds__(256)
void embpre_kernel(const float* __restrict__ W_ih0) {
    __shared__ __align__(16) float As[16][68];
    __shared__ __align__(16) float Bs[16][68];
    const int tid = threadIdx.x;
    const int m0 = blockIdx.y * 64, n0 = blockIdx.x * 64;
    const int lr = tid >> 2, lc = (tid & 3) * 4;
    const int tm = (tid >> 4) * 4, tn = (tid & 15) * 4;
    float acc[4][4] = {};
    for (int k0 = 0; k0 < 512; k0 += 16) {
        float4 av = *reinterpret_cast<const float4*>(g_embT + (m0 + lr) * 512 + k0 + lc);
        As[lc + 0][lr] = av.x; As[lc + 1][lr] = av.y; As[lc + 2][lr] = av.z; As[lc + 3][lr] = av.w;
        float4 wv = *reinterpret_cast<const float4*>(W_ih0 + (long long)(n0 + lr) * 1024 + k0 + lc);
        Bs[lc + 0][lr] = wv.x; Bs[lc + 1][lr] = wv.y; Bs[lc + 2][lr] = wv.z; Bs[lc + 3][lr] = wv.w;
        __syncthreads();
        #pragma unroll
        for (int kk = 0; kk < 16; kk++) {
            float4 a = *reinterpret_cast<const float4*>(&As[kk][tm]);
            float4 b = *reinterpret_cast<const float4*>(&Bs[kk][tn]);
            acc[0][0] += a.x * b.x; acc[0][1] += a.x * b.y; acc[0][2] += a.x * b.z; acc[0][3] += a.x * b.w;
            acc[1][0] += a.y * b.x; acc[1][1] += a.y * b.y; acc[1][2] += a.y * b.z; acc[1][3] += a.y * b.w;
            acc[2][0] += a.z * b.x; acc[2][1] += a.z * b.y; acc[2][2] += a.z * b.z; acc[2][3] += a.z * b.w;
            acc[3][0] += a.w * b.x; acc[3][1] += a.w * b.y; acc[3][2] += a.w * b.z; acc[3][3] += a.w * b.w;
        }
        __syncthreads();
    }
    #pragma unroll
    for (int i = 0; i < 4; i++) {
        float4 o = make_float4(acc[i][0], acc[i][1], acc[i][2], acc[i][3]);
        *reinterpret_cast<float4*>(g_embpre + (long long)(m0 + tm + i) * 2048 + n0 + tn) = o;
    }
}

// ---------------- persistent recurrence kernel ----------------
__device__ __forceinline__ float sigmf(float x) { return 1.f / (1.f + expf(-x)); }

__global__ __launch_bounds__(256, 1)
void decoder_persistent(const float* __restrict__ enc,
                        const float* __restrict__ W_a,
                        const float* __restrict__ W_ih0,
                        const float* __restrict__ W_hh0,
                        const float* __restrict__ b_ih0,
                        const float* __restrict__ b_hh0,
                        const float* __restrict__ W_ih1,
                        const float* __restrict__ W_hh1,
                        const float* __restrict__ b_ih1,
                        const float* __restrict__ b_hh1) {
    __shared__ __align__(16) float sA[64][33];
    __shared__ __align__(16) float sW[64][36];
    __shared__ float q_sm[512];
    __shared__ float sc[64];
    __shared__ float s_red[2];

    const int cta = blockIdx.x;
    const int tid = threadIdx.x;
    const int tr = tid >> 3;        // batch row 0..31
    const int tc = tid & 7;         // col group (4 cols)
    unsigned bar_t = 0;

    float* h0 = g_h;            float* h1 = g_h + 16384;
    float* c0 = g_c;            float* c1 = g_c + 16384;
    float* q  = g_qpart;
    float* g0hh = g_gpart;
    float* g1hh = g_gpart + 65536;
    float* p3   = g_gpart + 2 * 65536;   // [2][32][2048]
    float* p4   = g_gpart + 4 * 65536;   // [2][32][2048]

    auto gbar = [&]() {
        __syncthreads();
        __threadfence();
        bar_t += NCTA;
        if (tid == 0) {
            atomicAdd(&g_barcnt, 1u);
            while (*(volatile unsigned*)&g_barcnt < bar_t) { }
        }
        __syncthreads();
    };

    // C[32, 32cols@j0] (+)= A[32, k0:k0+nk] @ W[j0:j0+32, k0:k0+nk]^T
    auto tile32 = [&](const float* A, int sa, const float* W, int sw,
                      float* C, int ldc, int j0, int k0, int nk) {
        float a0 = 0.f, a1 = 0.f, a2 = 0.f, a3 = 0.f;
        for (int kc = 0; kc < nk; kc += 64) {
            #pragma unroll
            for (int r = 0; r < 2; r++) {
                int u = tid + r * 256;
                int row = u >> 4, kq = (u & 15) * 4;
                float4 x = __ldcg(reinterpret_cast<const float4*>(
                                      A + row * sa + k0 + kc + kq));
                sA[kq + 0][row] = x.x; sA[kq + 1][row] = x.y;
                sA[kq + 2][row] = x.z; sA[kq + 3][row] = x.w;
                float4 y = *reinterpret_cast<const float4*>(
                               W + (long long)(j0 + row) * sw + k0 + kc + kq);
                sW[kq + 0][row] = y.x; sW[kq + 1][row] = y.y;
                sW[kq + 2][row] = y.z; sW[kq + 3][row] = y.w;
            }
            __syncthreads();
            #pragma unroll 16
            for (int kk = 0; kk < 64; kk++) {
                float a = sA[kk][tr];
                float4 w = *reinterpret_cast<const float4*>(&sW[kk][tc * 4]);
                a0 += a * w.x; a1 += a * w.y; a2 += a * w.z; a3 += a * w.w;
            }
            __syncthreads();
        }
        *reinterpret_cast<float4*>(C + tr * ldc + j0 + tc * 4) =
            make_float4(a0, a1, a2, a3);
    };

    for (int t = 0; t < TT; t++) {
        float* feat_t = g_feat + t * 32768;
        const float* ep = g_embpre + (long long)t * 65536;

        // ---- P1: q = h1@W_a^T | g0hh = h0@Whh0^T | g1hh = h1@Whh1^T ----
        if (cta < 16)       tile32(h1, 512, W_a,   512, q,    512,  cta * 32,        0, 512);
        else if (cta < 80)  tile32(h0, 512, W_hh0, 512, g0hh, 2048, (cta - 16) * 32, 0, 512);
        else                tile32(h1, 512, W_hh1, 512, g1hh, 2048, (cta - 80) * 32, 0, 512);
        gbar();

        // ---- P2: attention (32 CTAs, one per batch) ----
        if (cta < 32) {
            const int b = cta;
            #pragma unroll
            for (int r = 0; r < 2; r++) {
                int k = tid + r * 256;
                q_sm[k] = __ldcg(q + b * 512 + k);
            }
            __syncthreads();
            const float* encb = enc + (long long)b * SS * 512;
            const int lane = tid & 31, warp = tid >> 5;
            #pragma unroll
            for (int si = 0; si < 8; si++) {
                int s = warp * 8 + si;
                const float* row = encb + s * 512;
                float sum = 0.f;
                for (int j = lane; j < 512; j += 32) sum += row[j] * q_sm[j];
                #pragma unroll
                for (int o = 16; o; o >>= 1) sum += __shfl_down_sync(0xffffffffu, sum, o);
                if (lane == 0) sc[s] = sum;
            }
            __syncthreads();
            if (tid == 0) {
                float mx = sc[0];
                for (int s = 1; s < 64; s++) mx = fmaxf(mx, sc[s]);
                s_red[0] = mx;
            }
            __syncthreads();
            if (tid < 64) sc[tid] = expf(sc[tid] - s_red[0]);
            __syncthreads();
            if (tid == 0) {
                float sm = 0.f;
                for (int s = 0; s < 64; s++) sm += sc[s];
                s_red[1] = 1.f / sm;
            }
            __syncthreads();
            const float inv = s_red[1];
            for (int k = tid; k < 512; k += 256) {
                float acc = 0.f;
                #pragma unroll 8
                for (int s = 0; s < 64; s++) acc += sc[s] * encb[s * 512 + k];
                feat_t[b * 1024 + 512 + k] = acc * inv;
            }
        }
        gbar();

        // ---- P3: ctx @ Wih0[:, 512:]^T (128 CTAs: 64 n-tiles x 2 k-halves) ----
        if (cta < 128) {
            int nt = cta >> 1, kh = cta & 1;
            tile32(feat_t + 512, 1024, W_ih0 + 512, 1024,
                   p3 + kh * 65536, 2048, nt * 32, kh * 256, 256);
        }
        gbar();

        // ---- P3b: LSTM0 update ----
        {
            int idx = cta * 256 + tid;
            if (idx < 16384) {
                int b = idx >> 9, u = idx & 511;
                int g = b * 2048 + u;
                float gi = ep[g]        + __ldcg(g0hh + g)        + __ldcg(p3 + g)         + __ldcg(p3 + 65536 + g)        + b_ih0[u]        + b_hh0[u];
                float gf = ep[g + 512]  + __ldcg(g0hh + g + 512)  + __ldcg(p3 + g + 512)   + __ldcg(p3 + 65536 + g + 512)  + b_ih0[512 + u]  + b_hh0[512 + u];
                float gg = ep[g + 1024] + __ldcg(g0hh + g + 1024) + __ldcg(p3 + g + 1024)  + __ldcg(p3 + 65536 + g + 1024) + b_ih0[1024 + u] + b_hh0[1024 + u];
                float go = ep[g + 1536] + __ldcg(g0hh + g + 1536) + __ldcg(p3 + g + 1536)  + __ldcg(p3 + 65536 + g + 1536) + b_ih0[1536 + u] + b_hh0[1536 + u];
                float cv = __ldcg(c0 + idx);
                float cn = sigmf(gf) * cv + sigmf(gi) * tanhf(gg);
                float hn = sigmf(go) * tanhf(cn);
                c0[idx] = cn;
                h0[idx] = hn;
            }
        }
        gbar();

        // ---- P4: h0 @ Wih1^T (128 CTAs) ----
        if (cta < 128) {
            int nt = cta >> 1, kh = cta & 1;
            tile32(h0, 512, W_ih1, 512,
                   p4 + kh * 65536, 2048, nt * 32, kh * 256, 256);
        }
        gbar();

        // ---- P4b: LSTM1 update + feat write ----
        {
            int idx = cta * 256 + tid;
            if (idx < 16384) {
                int b = idx >> 9, u = idx & 511;
                int g = b * 2048 + u;
                float gi = __ldcg(g1hh + g)        + __ldcg(p4 + g)        + __ldcg(p4 + 65536 + g)        + b_ih1[u]        + b_hh1[u];
                float gf = __ldcg(g1hh + g + 512)  + __ldcg(p4 + g + 512)  + __ldcg(p4 + 65536 + g + 512)  + b_ih1[512 + u]  + b_hh1[512 + u];
                float gg = __ldcg(g1hh + g + 1024) + __ldcg(p4 + g + 1024) + __ldcg(p4 + 65536 + g + 1024) + b_ih1[1024 + u] + b_hh1[1024 + u];
                float go = __ldcg(g1hh + g + 1536) + __ldcg(p4 + g + 1536) + __ldcg(p4 + 65536 + g + 1536) + b_ih1[1536 + u] + b_hh1[1536 + u];
                float cv = __ldcg(c1 + idx);
                float cn = sigmf(gf) * cv + sigmf(gi) * tanhf(gg);
                float hn = sigmf(go) * tanhf(cn);
                c1[idx] = cn;
                h1[idx] = hn;
                feat_t[b * 1024 + u] = hn;
            }
        }
        gbar();
    }
}

// ---------------- tensor-core projection GEMM (mma.sync, 3x bf16 split) -----
#define GK 1024
#define KC 32
#define NKC (GK / KC)
#define RST 40
#define BUF_BF16 (128 * RST)
#define STAGE_BF16 (4 * BUF_BF16)
#define GEMM_SMEM (2 * STAGE_BF16 * 2)

__global__ __launch_bounds__(256, 1)
void big_gemm_mma(const __nv_bfloat16* __restrict__ AH, const __nv_bfloat16* __restrict__ AL,
                  const __nv_bfloat16* __restrict__ BH, const __nv_bfloat16* __restrict__ BL,
                  const float* __restrict__ bias, float* __restrict__ out) {
    extern __shared__ __nv_bfloat16 sm[];
    const int tid = threadIdx.x;
    const int lane = tid & 31;
    const int wid = tid >> 5;
    const int wm = wid >> 1;
    const int wn = wid & 1;
    const int m0 = blockIdx.x * 128;
    const int n0 = blockIdx.y * 128;
    const uint32_t smem_base = smem_to_u32(sm);

    float acc[2][8][4];
    #pragma unroll
    for (int i = 0; i < 2; i++)
        #pragma unroll
        for (int j = 0; j < 8; j++)
            #pragma unroll
            for (int v = 0; v < 4; v++) acc[i][j][v] = 0.f;

    auto load_stage = [&](int st, int kc) {
        const uint32_t sb = smem_base + st * STAGE_BF16 * 2;
        const int k0 = kc * KC;
        #pragma unroll
        for (int r = 0; r < 2; r++) {
            int idx = tid + r * 256;
            int row = idx >> 2, c = idx & 3;
            uint32_t doff = (uint32_t)(row * RST + c * 8) * 2;
            long long aoff = (long long)(m0 + row) * GK + k0 + c * 8;
            long long boff = (long long)(n0 + row) * GK + k0 + c * 8;
            CP16(sb + doff,                AH + aoff);
            CP16(sb + BUF_BF16 * 2 + doff, AL + aoff);
            CP16(sb + BUF_BF16 * 4 + doff, BH + boff);
            CP16(sb + BUF_BF16 * 6 + doff, BL + boff);
        }
        CP_COMMIT();
    };

    load_stage(0, 0);

    for (int kc = 0; kc < NKC; kc++) {
        const int st = kc & 1;
        if (kc + 1 < NKC) { load_stage(st ^ 1, kc + 1); CP_WAIT1(); }
        else              { CP_WAIT0(); }
        __syncthreads();

        const uint32_t sb = smem_base + st * STAGE_BF16 * 2;
        uint32_t ah[2][2][4], al[2][2][4];
        #pragma unroll
        for (int i = 0; i < 2; i++)
            #pragma unroll
            for (int kk = 0; kk < 2; kk++) {
                uint32_t addr = sb + (uint32_t)((wm * 32 + i * 16 + (lane & 15)) * RST
                                                + kk * 16 + (lane >> 4) * 8) * 2;
                LDSM_X4(ah[i][kk][0], ah[i][kk][1], ah[i][kk][2], ah[i][kk][3], addr);
                LDSM_X4(al[i][kk][0], al[i][kk][1], al[i][kk][2], al[i][kk][3],
                        addr + BUF_BF16 * 2);
            }
        #pragma unroll
        for (int j = 0; j < 8; j++) {
            #pragma unroll
            for (int kk = 0; kk < 2; kk++) {
                uint32_t baddr = sb + BUF_BF16 * 4
                    + (uint32_t)((wn * 64 + j * 8 + (lane & 7)) * RST
                                 + kk * 16 + ((lane >> 3) & 1) * 8) * 2;
                uint32_t bh0, bh1, bl0, bl1;
                LDSM_X2(bh0, bh1, baddr);
                LDSM_X2(bl0, bl1, baddr + BUF_BF16 * 2);
                #pragma unroll
                for (int i = 0; i < 2; i++) {
                    MMA_BF16(acc[i][j], ah[i][kk][0], ah[i][kk][1], ah[i][kk][2], ah[i][kk][3], bh0, bh1);
                    MMA_BF16(acc[i][j], al[i][kk][0], al[i][kk][1], al[i][kk][2], al[i][kk][3], bh0, bh1);
                    MMA_BF16(acc[i][j], ah[i][kk][0], ah[i][kk][1], ah[i][kk][2], ah[i][kk][3], bl0, bl1);
                }
            }
        }
        __syncthreads();
    }

    #pragma unroll
    for (int i = 0; i < 2; i++) {
        int mA = m0 + wm * 32 + i * 16 + (lane >> 2);
        int mB = mA + 8;
        int tA = mA >> 5, bA = mA & 31;
        int tB = mB >> 5, bB = mB & 31;
        float* rowA = out + (long long)((bA << 6) + tA) * VV;
        float* rowB = out + (long long)((bB << 6) + tB) * VV;
        #pragma unroll
        for (int j = 0; j < 8; j++) {
            int n = n0 + wn * 64 + j * 8 + (lane & 3) * 2;
            float bv0 = bias[n], bv1 = bias[n + 1];
            float2 vA = make_float2(acc[i][j][0] + bv0, acc[i][j][1] + bv1);
            float2 vB = make_float2(acc[i][j][2] + bv0, acc[i][j][3] + bv1);
            *reinterpret_cast<float2*>(rowA + n) = vA;
            *reinterpret_cast<float2*>(rowB + n) = vB;
        }
    }
}

// ---------------- host launcher ----------------
extern "C" void kernel_launch(void* const* d_in, const int* in_sizes, int n_in,
                              void* d_out, int out_size) {
    const int*   tgt    = (const int*)  d_in[0];
    const float* enc    = (const float*)d_in[1];
    const float* hidden = (const float*)d_in[2];
    const float* cell   = (const float*)d_in[3];
    const float* emb    = (const float*)d_in[4];
    const float* W_a    = (const float*)d_in[5];
    const float* W_ih0  = (const float*)d_in[6];
    const float* W_hh0  = (const float*)d_in[7];
    const float* b_ih0  = (const float*)d_in[8];
    const float* b_hh0  = (const float*)d_in[9];
    const float* W_ih1  = (const float*)d_in[10];
    const float* W_hh1  = (const float*)d_in[11];
    const float* b_ih1  = (const float*)d_in[12];
    const float* b_hh1  = (const float*)d_in[13];
    const float* W_out  = (const float*)d_in[14];
    const float* b_out  = (const float*)d_in[15];
    float* out = (float*)d_out;

    float *p_feat;
    __nv_bfloat16 *p_WH, *p_WL, *p_fH, *p_fL;
    cudaGetSymbolAddress((void**)&p_feat, g_feat);
    cudaGetSymbolAddress((void**)&p_WH,   g_WH);
    cudaGetSymbolAddress((void**)&p_WL,   g_WL);
    cudaGetSymbolAddress((void**)&p_fH,   g_fH);
    cudaGetSymbolAddress((void**)&p_fL,   g_fL);

    init_state_kernel<<<64, 512>>>(hidden, cell);
    embed_kernel<<<BATCH * TT, 128>>>(tgt, emb);

    // precompute emb @ Wih0[:, :512]^T for all timesteps
    embpre_kernel<<<dim3(32, 32), 256>>>(W_ih0);

    // fused persistent recurrence (64 steps, grid barriers)
    decoder_persistent<<<NCTA, 256>>>(enc, W_a, W_ih0, W_hh0, b_ih0, b_hh0,
                                      W_ih1, W_hh1, b_ih1, b_hh1);

    // split W_out and feat into bf16 hi/lo
    split_bf16_kernel<<<4096, 256>>>((const float4*)W_out, (uint2*)p_WH, (uint2*)p_WL,
                                     VV * 1024 / 4);
    split_bf16_kernel<<<2048, 256>>>((const float4*)p_feat, (uint2*)p_fH, (uint2*)p_fL,
                                     2048 * 1024 / 4);

    // tensor-core projection
    cudaFuncSetAttribute(big_gemm_mma, cudaFuncAttributeMaxDynamicSharedMemorySize, GEMM_SMEM);
    big_gemm_mma<<<dim3(16, VV / 128), 256, GEMM_SMEM>>>(p_fH, p_fL, p_WH, p_WL, b_out, out);

    tail_copy_kernel<<<64, 512>>>(out);
}

// round 6
// speedup vs baseline: 1.1896x; 1.1896x over previous
#include <cuda_runtime.h>
#include <cuda_bf16.h>
#include <math.h>
#include <stdint.h>

// Problem constants
#define BATCH 32
#define TT 64
#define SS 64
#define VV 32000
#define EE 512
#define HH 512
#define NCTA 144

// ---------------- device scratch ----------------
__device__ unsigned short g_embH[2048 * 512];    // embedded bf16 hi, row = t*32+b
__device__ unsigned short g_embL[2048 * 512];
__device__ float g_h[2 * BATCH * HH];            // fp32 h (tail copy)
__device__ float g_c[2 * BATCH * HH];
__device__ unsigned short g_h0H[16384], g_h0L[16384];
__device__ unsigned short g_h1H[16384], g_h1L[16384];
__device__ unsigned short g_ctxH[16384], g_ctxL[16384];
__device__ float g_feat[TT * BATCH * 1024];      // [t][b][ h1 | ctx ]
__device__ float g_embpre[TT * BATCH * 2048];    // emb @ Wih0[:, :512]^T
__device__ float g_q4[4 * BATCH * 512];          // q k-slices
__device__ float g_g0hh[4 * BATCH * 2048];
__device__ float g_g1hh[4 * BATCH * 2048];
__device__ float g_g0ctx[4 * BATCH * 2048];
__device__ float g_g1ih[4 * BATCH * 2048];
__device__ unsigned g_barcnt;
// packed recurrence weights: [nt8][ki16][lane] uint4{b0h,b1h,b0l,b1l}
__device__ uint4 g_pkWa[64 * 32 * 32];
__device__ uint4 g_pkHH0[256 * 32 * 32];
__device__ uint4 g_pkHH1[256 * 32 * 32];
__device__ uint4 g_pkIH1[256 * 32 * 32];
__device__ uint4 g_pkIHC[256 * 32 * 32];
__device__ uint4 g_pkIH0[256 * 32 * 32];
// bf16 split operands for big projection GEMM
__device__ __nv_bfloat16 g_WH[VV * 1024];
__device__ __nv_bfloat16 g_WL[VV * 1024];
__device__ __nv_bfloat16 g_fH[2048 * 1024];
__device__ __nv_bfloat16 g_fL[2048 * 1024];

// ---------------- PTX helpers ----------------
__device__ __forceinline__ uint32_t smem_to_u32(const void* p) {
    uint32_t a;
    asm("{ .reg .u64 t; cvta.to.shared.u64 t, %1; cvt.u32.u64 %0, t; }" : "=r"(a) : "l"(p));
    return a;
}
#define CP16(dst, src) \
    asm volatile("cp.async.cg.shared.global [%0], [%1], 16;" \
                 :: "r"(dst), "l"(src) : "memory")
#define CP_COMMIT() asm volatile("cp.async.commit_group;" ::: "memory")
#define CP_WAIT0()  asm volatile("cp.async.wait_group 0;" ::: "memory")
#define CP_WAIT1()  asm volatile("cp.async.wait_group 1;" ::: "memory")

#define LDSM_X4(r0, r1, r2, r3, addr) \
    asm volatile("ldmatrix.sync.aligned.m8n8.x4.shared.b16 {%0,%1,%2,%3}, [%4];" \
                 : "=r"(r0), "=r"(r1), "=r"(r2), "=r"(r3) : "r"(addr))
#define LDSM_X2(r0, r1, addr) \
    asm volatile("ldmatrix.sync.aligned.m8n8.x2.shared.b16 {%0,%1}, [%2];" \
                 : "=r"(r0), "=r"(r1) : "r"(addr))

#define MMA_BF16(c, a0, a1, a2, a3, b0, b1) \
    asm volatile("mma.sync.aligned.m16n8k16.row.col.f32.bf16.bf16.f32 " \
                 "{%0,%1,%2,%3}, {%4,%5,%6,%7}, {%8,%9}, {%0,%1,%2,%3};" \
                 : "+f"((c)[0]), "+f"((c)[1]), "+f"((c)[2]), "+f"((c)[3]) \
                 : "r"(a0), "r"(a1), "r"(a2), "r"(a3), "r"(b0), "r"(b1))

__device__ __forceinline__ unsigned short bf16hi(float x) {
    return __bfloat16_as_ushort(__float2bfloat16(x));
}

// ---------------- utility kernels ----------------
__global__ void init_state_kernel(const float* __restrict__ hidden,
                                  const float* __restrict__ cell) {
    int i = blockIdx.x * blockDim.x + threadIdx.x;
    if (i == 0) g_barcnt = 0u;
    if (i < 2 * BATCH * HH) {
        float hv = hidden[i];
        g_h[i] = hv; g_c[i] = cell[i];
        unsigned short hi = bf16hi(hv);
        unsigned short lo = bf16hi(hv - __bfloat162float(__ushort_as_bfloat16(hi)));
        if (i < 16384) { g_h0H[i] = hi; g_h0L[i] = lo; }
        else           { g_h1H[i - 16384] = hi; g_h1L[i - 16384] = lo; }
    }
}

__global__ void tail_copy_kernel(float* __restrict__ out) {
    int i = blockIdx.x * blockDim.x + threadIdx.x;
    const long long OFF = (long long)BATCH * TT * VV;
    if (i < 2 * BATCH * HH) {
        out[OFF + i] = g_h[i];
        out[OFF + 2 * BATCH * HH + i] = g_c[i];
    }
}

// embedded row (t*32+b) as bf16 hi/lo duals
__global__ void embed_kernel(const int* __restrict__ tgt,
                             const float* __restrict__ emb) {
    int blk = blockIdx.x;             // b*TT + t
    int b = blk >> 6, t = blk & 63;
    int idx = tgt[blk];
    int e = threadIdx.x * 4;          // 128 threads x 4 elems
    float4 v;
    if (idx == 0) { v.x = v.y = v.z = v.w = 0.f; }
    else v = *reinterpret_cast<const float4*>(emb + (long long)idx * EE + e);
    unsigned short h0 = bf16hi(v.x), h1 = bf16hi(v.y), h2 = bf16hi(v.z), h3 = bf16hi(v.w);
    unsigned short l0 = bf16hi(v.x - __bfloat162float(__ushort_as_bfloat16(h0)));
    unsigned short l1 = bf16hi(v.y - __bfloat162float(__ushort_as_bfloat16(h1)));
    unsigned short l2 = bf16hi(v.z - __bfloat162float(__ushort_as_bfloat16(h2)));
    unsigned short l3 = bf16hi(v.w - __bfloat162float(__ushort_as_bfloat16(h3)));
    long long off = (long long)(t * 32 + b) * 512 + e;
    uint2 hv, lv;
    hv.x = (uint32_t)h0 | ((uint32_t)h1 << 16);
    hv.y = (uint32_t)h2 | ((uint32_t)h3 << 16);
    lv.x = (uint32_t)l0 | ((uint32_t)l1 << 16);
    lv.y = (uint32_t)l2 | ((uint32_t)l3 << 16);
    *reinterpret_cast<uint2*>(g_embH + off) = hv;
    *reinterpret_cast<uint2*>(g_embL + off) = lv;
}

// split fp32 -> bf16 hi + lo arrays (for big GEMM)
__global__ void split_bf16_kernel(const float4* __restrict__ in,
                                  uint2* __restrict__ hi, uint2* __restrict__ lo, int n4) {
    for (int i = blockIdx.x * blockDim.x + threadIdx.x; i < n4; i += gridDim.x * blockDim.x) {
        float4 x = in[i];
        unsigned short h0 = bf16hi(x.x), h1 = bf16hi(x.y), h2 = bf16hi(x.z), h3 = bf16hi(x.w);
        unsigned short l0 = bf16hi(x.x - __bfloat162float(__ushort_as_bfloat16(h0)));
        unsigned short l1 = bf16hi(x.y - __bfloat162float(__ushort_as_bfloat16(h1)));
        unsigned short l2 = bf16hi(x.z - __bfloat162float(__ushort_as_bfloat16(h2)));
        unsigned short l3 = bf16hi(x.w - __bfloat162float(__ushort_as_bfloat16(h3)));
        uint2 hv, lv;
        hv.x = (uint32_t)h0 | ((uint32_t)h1 << 16);
        hv.y = (uint32_t)h2 | ((uint32_t)h3 << 16);
        lv.x = (uint32_t)l0 | ((uint32_t)l1 << 16);
        lv.y = (uint32_t)l2 | ((uint32_t)l3 << 16);
        hi[i] = hv; lo[i] = lv;
    }
}

// pack W[n][k] fp32 -> fragment-ready hi/lo uint4, 1 block per n8-tile
__global__ void pack_kernel(const float* __restrict__ W, int sw,
                            uint4* __restrict__ dst) {
    int nt = blockIdx.x;
    int ki = threadIdx.x >> 5, lane = threadIdx.x & 31;
    int n = nt * 8 + (lane >> 2);
    int k = ki * 16 + (lane & 3) * 2;
    const float* w = W + (long long)n * sw + k;
    float v0 = w[0], v1 = w[1], v2 = w[8], v3 = w[9];
    unsigned short h0 = bf16hi(v0), h1 = bf16hi(v1), h2 = bf16hi(v2), h3 = bf16hi(v3);
    unsigned short l0 = bf16hi(v0 - __bfloat162float(__ushort_as_bfloat16(h0)));
    unsigned short l1 = bf16hi(v1 - __bfloat162float(__ushort_as_bfloat16(h1)));
    unsigned short l2 = bf16hi(v2 - __bfloat162float(__ushort_as_bfloat16(h2)));
    unsigned short l3 = bf16hi(v3 - __bfloat162float(__ushort_as_bfloat16(h3)));
    uint4 o;
    o.x = (uint32_t)h0 | ((uint32_t)h1 << 16);
    o.y = (uint32_t)h2 | ((uint32_t)h3 << 16);
    o.z = (uint32_t)l0 | ((uint32_t)l1 << 16);
    o.w = (uint32_t)l2 | ((uint32_t)l3 << 16);
    dst[(nt * 32 + ki) * 32 + lane] = o;
}

// ---------------- warp-level M=32 x N=32 bf16-split mma tile ----------------
// C[32, n0:n0+32] (fp32, ldc) = A[32, ki0*16 : (ki0+nki)*16] @ Wpk^T  (partial K)
__device__ __forceinline__ void mma_row32(
    const unsigned short* __restrict__ AH, const unsigned short* __restrict__ AL,
    const uint4* __restrict__ wpk, int nt0, int ki0, int nki,
    float* __restrict__ C, int ldc, int n0, int lane)
{
    float acc[2][4][4];
    #pragma unroll
    for (int mi = 0; mi < 2; mi++)
        #pragma unroll
        for (int nj = 0; nj < 4; nj++)
            #pragma unroll
            for (int v = 0; v < 4; v++) acc[mi][nj][v] = 0.f;

    const int r = lane >> 2;
    const int c2 = (lane & 3) * 2;
    const unsigned* pah = reinterpret_cast<const unsigned*>(AH + r * 512 + c2 + ki0 * 16);
    const unsigned* pal = reinterpret_cast<const unsigned*>(AL + r * 512 + c2 + ki0 * 16);
    const uint4* wp = wpk + ((nt0 * 32 + ki0) * 32 + lane);

    #pragma unroll 2
    for (int ki = 0; ki < nki; ki++) {
        unsigned ah[2][4], al[2][4];
        #pragma unroll
        for (int mi = 0; mi < 2; mi++) {
            const unsigned* p = pah + mi * 4096;     // +16 rows
            ah[mi][0] = __ldcg(p);
            ah[mi][1] = __ldcg(p + 2048);            // row +8
            ah[mi][2] = __ldcg(p + 4);               // k +8
            ah[mi][3] = __ldcg(p + 2052);
            const unsigned* q = pal + mi * 4096;
            al[mi][0] = __ldcg(q);
            al[mi][1] = __ldcg(q + 2048);
            al[mi][2] = __ldcg(q + 4);
            al[mi][3] = __ldcg(q + 2052);
        }
        #pragma unroll
        for (int nj = 0; nj < 4; nj++) {
            uint4 b = __ldg(wp + nj * 1024);
            #pragma unroll
            for (int mi = 0; mi < 2; mi++) {
                MMA_BF16(acc[mi][nj], ah[mi][0], ah[mi][1], ah[mi][2], ah[mi][3], b.x, b.y);
                MMA_BF16(acc[mi][nj], al[mi][0], al[mi][1], al[mi][2], al[mi][3], b.x, b.y);
                MMA_BF16(acc[mi][nj], ah[mi][0], ah[mi][1], ah[mi][2], ah[mi][3], b.z, b.w);
            }
        }
        pah += 8; pal += 8; wp += 32;
    }
    #pragma unroll
    for (int mi = 0; mi < 2; mi++)
        #pragma unroll
        for (int nj = 0; nj < 4; nj++) {
            int col = n0 + nj * 8 + c2;
            *reinterpret_cast<float2*>(C + (mi * 16 + r) * ldc + col) =
                make_float2(acc[mi][nj][0], acc[mi][nj][1]);
            *reinterpret_cast<float2*>(C + (mi * 16 + 8 + r) * ldc + col) =
                make_float2(acc[mi][nj][2], acc[mi][nj][3]);
        }
}

// ---------------- embpre: [2048,2048] = emb @ Wih0[:, :512]^T ----------------
__global__ __launch_bounds__(256)
void embpre_mma_kernel() {
    int g = blockIdx.x * 8 + (threadIdx.x >> 5);   // 0..4095
    int lane = threadIdx.x & 31;
    int rb = g >> 6;        // 64 row blocks of 32
    int nt = g & 63;        // 64 n32 tiles
    mma_row32(g_embH + rb * 32 * 512, g_embL + rb * 32 * 512,
              g_pkIH0, nt * 4, 0, 32,
              g_embpre + (long long)rb * 32 * 2048, 2048, nt * 32, lane);
}

// ---------------- persistent recurrence ----------------
__device__ __forceinline__ float sigmf(float x) { return 1.f / (1.f + expf(-x)); }

__global__ __launch_bounds__(256, 1)
void decoder_persistent(const float* __restrict__ enc,
                        const float* __restrict__ b_ih0,
                        const float* __restrict__ b_hh0,
                        const float* __restrict__ b_ih1,
                        const float* __restrict__ b_hh1) {
    __shared__ float q_sm[512];
    __shared__ float sc[64];
    __shared__ float s_red[2];

    const int cta = blockIdx.x;
    const int tid = threadIdx.x;
    const int lane = tid & 31;
    const int wid = tid >> 5;
    const int g = cta * 8 + wid;
    unsigned bar_t = 0;

    auto gbar = [&]() {
        __syncthreads();
        __threadfence();
        bar_t += NCTA;
        if (tid == 0) {
            atomicAdd(&g_barcnt, 1u);
            while (*(volatile unsigned*)&g_barcnt < bar_t) { }
        }
        __syncthreads();
    };

    for (int t = 0; t < TT; t++) {
        float* feat_t = g_feat + t * 32768;
        const float* ep = g_embpre + (long long)t * 65536;

        // ---- P1: q = h1@Wa^T | g0hh = h0@Whh0^T | g1hh = h1@Whh1^T (k-split 4)
        if (g < 576) {
            int ks = g & 3, nt_ = g >> 2;
            int ki0 = ks * 8;
            if (nt_ < 16)
                mma_row32(g_h1H, g_h1L, g_pkWa, nt_ * 4, ki0, 8,
                          g_q4 + ks * 16384, 512, nt_ * 32, lane);
            else if (nt_ < 80)
                mma_row32(g_h0H, g_h0L, g_pkHH0, (nt_ - 16) * 4, ki0, 8,
                          g_g0hh + ks * 65536, 2048, (nt_ - 16) * 32, lane);
            else
                mma_row32(g_h1H, g_h1L, g_pkHH1, (nt_ - 80) * 4, ki0, 8,
                          g_g1hh + ks * 65536, 2048, (nt_ - 80) * 32, lane);
        }
        gbar();

        // ---- P2: attention (32 CTAs) ----
        if (cta < 32) {
            const int b = cta;
            #pragma unroll
            for (int r = 0; r < 2; r++) {
                int k = tid + r * 256;
                float v = 0.f;
                #pragma unroll
                for (int s = 0; s < 4; s++) v += __ldcg(g_q4 + s * 16384 + b * 512 + k);
                q_sm[k] = v;
            }
            __syncthreads();
            const float* encb = enc + (long long)b * SS * 512;
            #pragma unroll
            for (int si = 0; si < 8; si++) {
                int s = wid * 8 + si;
                const float* row = encb + s * 512;
                float sum = 0.f;
                for (int j = lane; j < 512; j += 32) sum += row[j] * q_sm[j];
                #pragma unroll
                for (int o = 16; o; o >>= 1) sum += __shfl_down_sync(0xffffffffu, sum, o);
                if (lane == 0) sc[s] = sum;
            }
            __syncthreads();
            if (tid == 0) {
                float mx = sc[0];
                for (int s = 1; s < 64; s++) mx = fmaxf(mx, sc[s]);
                s_red[0] = mx;
            }
            __syncthreads();
            if (tid < 64) sc[tid] = expf(sc[tid] - s_red[0]);
            __syncthreads();
            if (tid == 0) {
                float sm = 0.f;
                for (int s = 0; s < 64; s++) sm += sc[s];
                s_red[1] = 1.f / sm;
            }
            __syncthreads();
            const float inv = s_red[1];
            for (int k = tid; k < 512; k += 256) {
                float acc = 0.f;
                #pragma unroll 8
                for (int s = 0; s < 64; s++) acc += sc[s] * encb[s * 512 + k];
                float cv = acc * inv;
                feat_t[b * 1024 + 512 + k] = cv;
                unsigned short hi = bf16hi(cv);
                unsigned short lo = bf16hi(cv - __bfloat162float(__ushort_as_bfloat16(hi)));
                g_ctxH[b * 512 + k] = hi;
                g_ctxL[b * 512 + k] = lo;
            }
        }
        gbar();

        // ---- P3: g0ctx = ctx @ Wihc^T (k-split 4) ----
        if (g < 256) {
            int ks = g & 3, nt_ = g >> 2;
            mma_row32(g_ctxH, g_ctxL, g_pkIHC, nt_ * 4, ks * 8, 8,
                      g_g0ctx + ks * 65536, 2048, nt_ * 32, lane);
        }
        gbar();

        // ---- P3b: LSTM0 update ----
        {
            int idx = cta * 256 + tid;
            if (idx < 16384) {
                int b = idx >> 9, u = idx & 511;
                int gg0 = b * 2048 + u;
                float gv[4];
                #pragma unroll
                for (int q = 0; q < 4; q++) {
                    int o = gg0 + q * 512;
                    float v = ep[o];
                    #pragma unroll
                    for (int s = 0; s < 4; s++) {
                        v += __ldcg(g_g0hh + s * 65536 + o);
                        v += __ldcg(g_g0ctx + s * 65536 + o);
                    }
                    gv[q] = v + b_ih0[q * 512 + u] + b_hh0[q * 512 + u];
                }
                float cv = __ldcg(g_c + idx);
                float cn = sigmf(gv[1]) * cv + sigmf(gv[0]) * tanhf(gv[2]);
                float hn = sigmf(gv[3]) * tanhf(cn);
                g_c[idx] = cn;
                g_h[idx] = hn;
                unsigned short hi = bf16hi(hn);
                unsigned short lo = bf16hi(hn - __bfloat162float(__ushort_as_bfloat16(hi)));
                g_h0H[idx] = hi;
                g_h0L[idx] = lo;
            }
        }
        gbar();

        // ---- P4: g1ih = h0 @ Wih1^T (k-split 4) ----
        if (g < 256) {
            int ks = g & 3, nt_ = g >> 2;
            mma_row32(g_h0H, g_h0L, g_pkIH1, nt_ * 4, ks * 8, 8,
                      g_g1ih + ks * 65536, 2048, nt_ * 32, lane);
        }
        gbar();

        // ---- P4b: LSTM1 update + feat write ----
        {
            int idx = cta * 256 + tid;
            if (idx < 16384) {
                int b = idx >> 9, u = idx & 511;
                int gg0 = b * 2048 + u;
                float gv[4];
                #pragma unroll
                for (int q = 0; q < 4; q++) {
                    int o = gg0 + q * 512;
                    float v = 0.f;
                    #pragma unroll
                    for (int s = 0; s < 4; s++) {
                        v += __ldcg(g_g1hh + s * 65536 + o);
                        v += __ldcg(g_g1ih + s * 65536 + o);
                    }
                    gv[q] = v + b_ih1[q * 512 + u] + b_hh1[q * 512 + u];
                }
                float cv = __ldcg(g_c + 16384 + idx);
                float cn = sigmf(gv[1]) * cv + sigmf(gv[0]) * tanhf(gv[2]);
                float hn = sigmf(gv[3]) * tanhf(cn);
                g_c[16384 + idx] = cn;
                g_h[16384 + idx] = hn;
                feat_t[b * 1024 + u] = hn;
                unsigned short hi = bf16hi(hn);
                unsigned short lo = bf16hi(hn - __bfloat162float(__ushort_as_bfloat16(hi)));
                g_h1H[idx] = hi;
                g_h1L[idx] = lo;
            }
        }
        gbar();
    }
}

// ---------------- big projection GEMM (unchanged from R4) ----------------
#define GK 1024
#define KC 32
#define NKC (GK / KC)
#define RST 40
#define BUF_BF16 (128 * RST)
#define STAGE_BF16 (4 * BUF_BF16)
#define GEMM_SMEM (2 * STAGE_BF16 * 2)

__global__ __launch_bounds__(256, 1)
void big_gemm_mma(const __nv_bfloat16* __restrict__ AH, const __nv_bfloat16* __restrict__ AL,
                  const __nv_bfloat16* __restrict__ BH, const __nv_bfloat16* __restrict__ BL,
                  const float* __restrict__ bias, float* __restrict__ out) {
    extern __shared__ __nv_bfloat16 sm[];
    const int tid = threadIdx.x;
    const int lane = tid & 31;
    const int wid = tid >> 5;
    const int wm = wid >> 1;
    const int wn = wid & 1;
    const int m0 = blockIdx.x * 128;
    const int n0 = blockIdx.y * 128;
    const uint32_t smem_base = smem_to_u32(sm);

    float acc[2][8][4];
    #pragma unroll
    for (int i = 0; i < 2; i++)
        #pragma unroll
        for (int j = 0; j < 8; j++)
            #pragma unroll
            for (int v = 0; v < 4; v++) acc[i][j][v] = 0.f;

    auto load_stage = [&](int st, int kc) {
        const uint32_t sb = smem_base + st * STAGE_BF16 * 2;
        const int k0 = kc * KC;
        #pragma unroll
        for (int r = 0; r < 2; r++) {
            int idx = tid + r * 256;
            int row = idx >> 2, c = idx & 3;
            uint32_t doff = (uint32_t)(row * RST + c * 8) * 2;
            long long aoff = (long long)(m0 + row) * GK + k0 + c * 8;
            long long boff = (long long)(n0 + row) * GK + k0 + c * 8;
            CP16(sb + doff,                AH + aoff);
            CP16(sb + BUF_BF16 * 2 + doff, AL + aoff);
            CP16(sb + BUF_BF16 * 4 + doff, BH + boff);
            CP16(sb + BUF_BF16 * 6 + doff, BL + boff);
        }
        CP_COMMIT();
    };

    load_stage(0, 0);

    for (int kc = 0; kc < NKC; kc++) {
        const int st = kc & 1;
        if (kc + 1 < NKC) { load_stage(st ^ 1, kc + 1); CP_WAIT1(); }
        else              { CP_WAIT0(); }
        __syncthreads();

        const uint32_t sb = smem_base + st * STAGE_BF16 * 2;
        uint32_t ah[2][2][4], al[2][2][4];
        #pragma unroll
        for (int i = 0; i < 2; i++)
            #pragma unroll
            for (int kk = 0; kk < 2; kk++) {
                uint32_t addr = sb + (uint32_t)((wm * 32 + i * 16 + (lane & 15)) * RST
                                                + kk * 16 + (lane >> 4) * 8) * 2;
                LDSM_X4(ah[i][kk][0], ah[i][kk][1], ah[i][kk][2], ah[i][kk][3], addr);
                LDSM_X4(al[i][kk][0], al[i][kk][1], al[i][kk][2], al[i][kk][3],
                        addr + BUF_BF16 * 2);
            }
        #pragma unroll
        for (int j = 0; j < 8; j++) {
            #pragma unroll
            for (int kk = 0; kk < 2; kk++) {
                uint32_t baddr = sb + BUF_BF16 * 4
                    + (uint32_t)((wn * 64 + j * 8 + (lane & 7)) * RST
                                 + kk * 16 + ((lane >> 3) & 1) * 8) * 2;
                uint32_t bh0, bh1, bl0, bl1;
                LDSM_X2(bh0, bh1, baddr);
                LDSM_X2(bl0, bl1, baddr + BUF_BF16 * 2);
                #pragma unroll
                for (int i = 0; i < 2; i++) {
                    MMA_BF16(acc[i][j], ah[i][kk][0], ah[i][kk][1], ah[i][kk][2], ah[i][kk][3], bh0, bh1);
                    MMA_BF16(acc[i][j], al[i][kk][0], al[i][kk][1], al[i][kk][2], al[i][kk][3], bh0, bh1);
                    MMA_BF16(acc[i][j], ah[i][kk][0], ah[i][kk][1], ah[i][kk][2], ah[i][kk][3], bl0, bl1);
                }
            }
        }
        __syncthreads();
    }

    #pragma unroll
    for (int i = 0; i < 2; i++) {
        int mA = m0 + wm * 32 + i * 16 + (lane >> 2);
        int mB = mA + 8;
        int tA = mA >> 5, bA = mA & 31;
        int tB = mB >> 5, bB = mB & 31;
        float* rowA = out + (long long)((bA << 6) + tA) * VV;
        float* rowB = out + (long long)((bB << 6) + tB) * VV;
        #pragma unroll
        for (int j = 0; j < 8; j++) {
            int n = n0 + wn * 64 + j * 8 + (lane & 3) * 2;
            float bv0 = bias[n], bv1 = bias[n + 1];
            float2 vA = make_float2(acc[i][j][0] + bv0, acc[i][j][1] + bv1);
            float2 vB = make_float2(acc[i][j][2] + bv0, acc[i][j][3] + bv1);
            *reinterpret_cast<float2*>(rowA + n) = vA;
            *reinterpret_cast<float2*>(rowB + n) = vB;
        }
    }
}

// ---------------- host launcher ----------------
extern "C" void kernel_launch(void* const* d_in, const int* in_sizes, int n_in,
                              void* d_out, int out_size) {
    const int*   tgt    = (const int*)  d_in[0];
    const float* enc    = (const float*)d_in[1];
    const float* hidden = (const float*)d_in[2];
    const float* cell   = (const float*)d_in[3];
    const float* emb    = (const float*)d_in[4];
    const float* W_a    = (const float*)d_in[5];
    const float* W_ih0  = (const float*)d_in[6];
    const float* W_hh0  = (const float*)d_in[7];
    const float* b_ih0  = (const float*)d_in[8];
    const float* b_hh0  = (const float*)d_in[9];
    const float* W_ih1  = (const float*)d_in[10];
    const float* W_hh1  = (const float*)d_in[11];
    const float* b_ih1  = (const float*)d_in[12];
    const float* b_hh1  = (const float*)d_in[13];
    const float* W_out  = (const float*)d_in[14];
    const float* b_out  = (const float*)d_in[15];
    float* out = (float*)d_out;

    float *p_feat;
    __nv_bfloat16 *p_WH, *p_WL, *p_fH, *p_fL;
    uint4 *pkWa, *pkHH0, *pkHH1, *pkIH1, *pkIHC, *pkIH0;
    cudaGetSymbolAddress((void**)&p_feat, g_feat);
    cudaGetSymbolAddress((void**)&p_WH,   g_WH);
    cudaGetSymbolAddress((void**)&p_WL,   g_WL);
    cudaGetSymbolAddress((void**)&p_fH,   g_fH);
    cudaGetSymbolAddress((void**)&p_fL,   g_fL);
    cudaGetSymbolAddress((void**)&pkWa,   g_pkWa);
    cudaGetSymbolAddress((void**)&pkHH0,  g_pkHH0);
    cudaGetSymbolAddress((void**)&pkHH1,  g_pkHH1);
    cudaGetSymbolAddress((void**)&pkIH1,  g_pkIH1);
    cudaGetSymbolAddress((void**)&pkIHC,  g_pkIHC);
    cudaGetSymbolAddress((void**)&pkIH0,  g_pkIH0);

    init_state_kernel<<<64, 512>>>(hidden, cell);
    embed_kernel<<<BATCH * TT, 128>>>(tgt, emb);

    // pack recurrence weights (fragment-ready bf16 hi/lo)
    pack_kernel<<<64,  1024>>>(W_a,         512,  pkWa);
    pack_kernel<<<256, 1024>>>(W_hh0,       512,  pkHH0);
    pack_kernel<<<256, 1024>>>(W_hh1,       512,  pkHH1);
    pack_kernel<<<256, 1024>>>(W_ih1,       512,  pkIH1);
    pack_kernel<<<256, 1024>>>(W_ih0 + 512, 1024, pkIHC);
    pack_kernel<<<256, 1024>>>(W_ih0,       1024, pkIH0);

    // precompute emb @ Wih0[:, :512]^T (tensor path)
    embpre_mma_kernel<<<512, 256>>>();

    // fused persistent recurrence
    decoder_persistent<<<NCTA, 256>>>(enc, b_ih0, b_hh0, b_ih1, b_hh1);

    // split W_out and feat for big GEMM
    split_bf16_kernel<<<4096, 256>>>((const float4*)W_out, (uint2*)p_WH, (uint2*)p_WL,
                                     VV * 1024 / 4);
    split_bf16_kernel<<<2048, 256>>>((const float4*)p_feat, (uint2*)p_fH, (uint2*)p_fL,
                                     2048 * 1024 / 4);

    // tensor-core projection
    cudaFuncSetAttribute(big_gemm_mma, cudaFuncAttributeMaxDynamicSharedMemorySize, GEMM_SMEM);
    big_gemm_mma<<<dim3(16, VV / 128), 256, GEMM_SMEM>>>(p_fH, p_fL, p_WH, p_WL, b_out, out);

    tail_copy_kernel<<<64, 512>>>(out);
}

// round 7
// speedup vs baseline: 1.3704x; 1.1520x over previous
#include <cuda_runtime.h>
#include <cuda_bf16.h>
#include <math.h>
#include <stdint.h>

// Problem constants
#define BATCH 32
#define TT 64
#define SS 64
#define VV 32000
#define EE 512
#define HH 512
#define NCTA 144

// ---------------- device scratch ----------------
__device__ unsigned short g_embH[2048 * 512];    // embedded bf16 hi, row = t*32+b
__device__ unsigned short g_embL[2048 * 512];
__device__ unsigned short g_encH[2048 * 512];    // enc bf16 duals, row = b*64+s
__device__ unsigned short g_encL[2048 * 512];
__device__ float g_encproj[2048 * 512];          // enc @ W_a, row = b*64+s
__device__ float g_h[2 * BATCH * HH];            // fp32 h (tail copy)
__device__ float g_c[2 * BATCH * HH];
__device__ unsigned short g_h0H[16384], g_h0L[16384];
__device__ unsigned short g_h1H[16384], g_h1L[16384];
__device__ unsigned short g_ctxH[16384], g_ctxL[16384];
__device__ float g_feat[TT * BATCH * 1024];      // [t][b][ h1 | ctx ]
__device__ float g_embpre[TT * BATCH * 2048];    // emb @ Wih0[:, :512]^T
__device__ float g_g0hh[4 * BATCH * 2048];
__device__ float g_g1hh[4 * BATCH * 2048];
__device__ float g_g0ctx[8 * BATCH * 2048];
__device__ float g_g1ih[8 * BATCH * 2048];
__device__ unsigned g_barcnt;
// packed weights: [nt8][ki16][lane] uint4{b0h,b1h,b0l,b1l}
__device__ uint4 g_pkWaT[64 * 32 * 32];          // W_a^T packed (for encproj)
__device__ uint4 g_pkHH0[256 * 32 * 32];
__device__ uint4 g_pkHH1[256 * 32 * 32];
__device__ uint4 g_pkIH1[256 * 32 * 32];
__device__ uint4 g_pkIHC[256 * 32 * 32];
__device__ uint4 g_pkIH0[256 * 32 * 32];
// bf16 split operands for big projection GEMM
__device__ __nv_bfloat16 g_WH[VV * 1024];
__device__ __nv_bfloat16 g_WL[VV * 1024];
__device__ __nv_bfloat16 g_fH[2048 * 1024];
__device__ __nv_bfloat16 g_fL[2048 * 1024];

// ---------------- PTX helpers ----------------
__device__ __forceinline__ uint32_t smem_to_u32(const void* p) {
    uint32_t a;
    asm("{ .reg .u64 t; cvta.to.shared.u64 t, %1; cvt.u32.u64 %0, t; }" : "=r"(a) : "l"(p));
    return a;
}
#define CP16(dst, src) \
    asm volatile("cp.async.cg.shared.global [%0], [%1], 16;" \
                 :: "r"(dst), "l"(src) : "memory")
#define CP_COMMIT() asm volatile("cp.async.commit_group;" ::: "memory")
#define CP_WAIT0()  asm volatile("cp.async.wait_group 0;" ::: "memory")
#define CP_WAIT1()  asm volatile("cp.async.wait_group 1;" ::: "memory")

#define LDSM_X4(r0, r1, r2, r3, addr) \
    asm volatile("ldmatrix.sync.aligned.m8n8.x4.shared.b16 {%0,%1,%2,%3}, [%4];" \
                 : "=r"(r0), "=r"(r1), "=r"(r2), "=r"(r3) : "r"(addr))
#define LDSM_X2(r0, r1, addr) \
    asm volatile("ldmatrix.sync.aligned.m8n8.x2.shared.b16 {%0,%1}, [%2];" \
                 : "=r"(r0), "=r"(r1) : "r"(addr))

#define MMA_BF16(c, a0, a1, a2, a3, b0, b1) \
    asm volatile("mma.sync.aligned.m16n8k16.row.col.f32.bf16.bf16.f32 " \
                 "{%0,%1,%2,%3}, {%4,%5,%6,%7}, {%8,%9}, {%0,%1,%2,%3};" \
                 : "+f"((c)[0]), "+f"((c)[1]), "+f"((c)[2]), "+f"((c)[3]) \
                 : "r"(a0), "r"(a1), "r"(a2), "r"(a3), "r"(b0), "r"(b1))

__device__ __forceinline__ unsigned short bf16hi(float x) {
    return __bfloat16_as_ushort(__float2bfloat16(x));
}

// ---------------- utility kernels ----------------
__global__ void init_state_kernel(const float* __restrict__ hidden,
                                  const float* __restrict__ cell) {
    int i = blockIdx.x * blockDim.x + threadIdx.x;
    if (i == 0) g_barcnt = 0u;
    if (i < 2 * BATCH * HH) {
        float hv = hidden[i];
        g_h[i] = hv; g_c[i] = cell[i];
        unsigned short hi = bf16hi(hv);
        unsigned short lo = bf16hi(hv - __bfloat162float(__ushort_as_bfloat16(hi)));
        if (i < 16384) { g_h0H[i] = hi; g_h0L[i] = lo; }
        else           { g_h1H[i - 16384] = hi; g_h1L[i - 16384] = lo; }
    }
}

__global__ void tail_copy_kernel(float* __restrict__ out) {
    int i = blockIdx.x * blockDim.x + threadIdx.x;
    const long long OFF = (long long)BATCH * TT * VV;
    if (i < 2 * BATCH * HH) {
        out[OFF + i] = g_h[i];
        out[OFF + 2 * BATCH * HH + i] = g_c[i];
    }
}

__global__ void embed_kernel(const int* __restrict__ tgt,
                             const float* __restrict__ emb) {
    int blk = blockIdx.x;             // b*TT + t
    int b = blk >> 6, t = blk & 63;
    int idx = tgt[blk];
    int e = threadIdx.x * 4;
    float4 v;
    if (idx == 0) { v.x = v.y = v.z = v.w = 0.f; }
    else v = *reinterpret_cast<const float4*>(emb + (long long)idx * EE + e);
    unsigned short h0 = bf16hi(v.x), h1 = bf16hi(v.y), h2 = bf16hi(v.z), h3 = bf16hi(v.w);
    unsigned short l0 = bf16hi(v.x - __bfloat162float(__ushort_as_bfloat16(h0)));
    unsigned short l1 = bf16hi(v.y - __bfloat162float(__ushort_as_bfloat16(h1)));
    unsigned short l2 = bf16hi(v.z - __bfloat162float(__ushort_as_bfloat16(h2)));
    unsigned short l3 = bf16hi(v.w - __bfloat162float(__ushort_as_bfloat16(h3)));
    long long off = (long long)(t * 32 + b) * 512 + e;
    uint2 hv, lv;
    hv.x = (uint32_t)h0 | ((uint32_t)h1 << 16);
    hv.y = (uint32_t)h2 | ((uint32_t)h3 << 16);
    lv.x = (uint32_t)l0 | ((uint32_t)l1 << 16);
    lv.y = (uint32_t)l2 | ((uint32_t)l3 << 16);
    *reinterpret_cast<uint2*>(g_embH + off) = hv;
    *reinterpret_cast<uint2*>(g_embL + off) = lv;
}

__global__ void split_bf16_kernel(const float4* __restrict__ in,
                                  uint2* __restrict__ hi, uint2* __restrict__ lo, int n4) {
    for (int i = blockIdx.x * blockDim.x + threadIdx.x; i < n4; i += gridDim.x * blockDim.x) {
        float4 x = in[i];
        unsigned short h0 = bf16hi(x.x), h1 = bf16hi(x.y), h2 = bf16hi(x.z), h3 = bf16hi(x.w);
        unsigned short l0 = bf16hi(x.x - __bfloat162float(__ushort_as_bfloat16(h0)));
        unsigned short l1 = bf16hi(x.y - __bfloat162float(__ushort_as_bfloat16(h1)));
        unsigned short l2 = bf16hi(x.z - __bfloat162float(__ushort_as_bfloat16(h2)));
        unsigned short l3 = bf16hi(x.w - __bfloat162float(__ushort_as_bfloat16(h3)));
        uint2 hv, lv;
        hv.x = (uint32_t)h0 | ((uint32_t)h1 << 16);
        hv.y = (uint32_t)h2 | ((uint32_t)h3 << 16);
        lv.x = (uint32_t)l0 | ((uint32_t)l1 << 16);
        lv.y = (uint32_t)l2 | ((uint32_t)l3 << 16);
        hi[i] = hv; lo[i] = lv;
    }
}

// pack W[n][k] -> fragment-ready hi/lo uint4
__global__ void pack_kernel(const float* __restrict__ W, int sw,
                            uint4* __restrict__ dst) {
    int nt = blockIdx.x;
    int ki = threadIdx.x >> 5, lane = threadIdx.x & 31;
    int n = nt * 8 + (lane >> 2);
    int k = ki * 16 + (lane & 3) * 2;
    const float* w = W + (long long)n * sw + k;
    float v0 = w[0], v1 = w[1], v2 = w[8], v3 = w[9];
    unsigned short h0 = bf16hi(v0), h1 = bf16hi(v1), h2 = bf16hi(v2), h3 = bf16hi(v3);
    unsigned short l0 = bf16hi(v0 - __bfloat162float(__ushort_as_bfloat16(h0)));
    unsigned short l1 = bf16hi(v1 - __bfloat162float(__ushort_as_bfloat16(h1)));
    unsigned short l2 = bf16hi(v2 - __bfloat162float(__ushort_as_bfloat16(h2)));
    unsigned short l3 = bf16hi(v3 - __bfloat162float(__ushort_as_bfloat16(h3)));
    uint4 o;
    o.x = (uint32_t)h0 | ((uint32_t)h1 << 16);
    o.y = (uint32_t)h2 | ((uint32_t)h3 << 16);
    o.z = (uint32_t)l0 | ((uint32_t)l1 << 16);
    o.w = (uint32_t)l2 | ((uint32_t)l3 << 16);
    dst[(nt * 32 + ki) * 32 + lane] = o;
}

// pack W^T: dst acts as W'[n][k] = W[k][n]
__global__ void pack_t_kernel(const float* __restrict__ W, int sw,
                              uint4* __restrict__ dst) {
    int nt = blockIdx.x;
    int ki = threadIdx.x >> 5, lane = threadIdx.x & 31;
    int n = nt * 8 + (lane >> 2);
    int k = ki * 16 + (lane & 3) * 2;
    const float* w = W + (long long)k * sw + n;
    float v0 = w[0], v1 = w[sw], v2 = w[8 * sw], v3 = w[9 * sw];
    unsigned short h0 = bf16hi(v0), h1 = bf16hi(v1), h2 = bf16hi(v2), h3 = bf16hi(v3);
    unsigned short l0 = bf16hi(v0 - __bfloat162float(__ushort_as_bfloat16(h0)));
    unsigned short l1 = bf16hi(v1 - __bfloat162float(__ushort_as_bfloat16(h1)));
    unsigned short l2 = bf16hi(v2 - __bfloat162float(__ushort_as_bfloat16(h2)));
    unsigned short l3 = bf16hi(v3 - __bfloat162float(__ushort_as_bfloat16(h3)));
    uint4 o;
    o.x = (uint32_t)h0 | ((uint32_t)h1 << 16);
    o.y = (uint32_t)h2 | ((uint32_t)h3 << 16);
    o.z = (uint32_t)l0 | ((uint32_t)l1 << 16);
    o.w = (uint32_t)l2 | ((uint32_t)l3 << 16);
    dst[(nt * 32 + ki) * 32 + lane] = o;
}

// ---------------- warp-level M=32 x N=32 4-term bf16-split mma tile ---------
__device__ __forceinline__ void mma_row32(
    const unsigned short* __restrict__ AH, const unsigned short* __restrict__ AL,
    const uint4* __restrict__ wpk, int nt0, int ki0, int nki,
    float* __restrict__ C, int ldc, int n0, int lane)
{
    float acc[2][4][4];
    #pragma unroll
    for (int mi = 0; mi < 2; mi++)
        #pragma unroll
        for (int nj = 0; nj < 4; nj++)
            #pragma unroll
            for (int v = 0; v < 4; v++) acc[mi][nj][v] = 0.f;

    const int r = lane >> 2;
    const int c2 = (lane & 3) * 2;
    const unsigned* pah = reinterpret_cast<const unsigned*>(AH + r * 512 + c2 + ki0 * 16);
    const unsigned* pal = reinterpret_cast<const unsigned*>(AL + r * 512 + c2 + ki0 * 16);
    const uint4* wp = wpk + ((nt0 * 32 + ki0) * 32 + lane);

    #pragma unroll 2
    for (int ki = 0; ki < nki; ki++) {
        unsigned ah[2][4], al[2][4];
        #pragma unroll
        for (int mi = 0; mi < 2; mi++) {
            const unsigned* p = pah + mi * 4096;
            ah[mi][0] = __ldcg(p);
            ah[mi][1] = __ldcg(p + 2048);
            ah[mi][2] = __ldcg(p + 4);
            ah[mi][3] = __ldcg(p + 2052);
            const unsigned* q = pal + mi * 4096;
            al[mi][0] = __ldcg(q);
            al[mi][1] = __ldcg(q + 2048);
            al[mi][2] = __ldcg(q + 4);
            al[mi][3] = __ldcg(q + 2052);
        }
        #pragma unroll
        for (int nj = 0; nj < 4; nj++) {
            uint4 b = __ldg(wp + nj * 1024);
            #pragma unroll
            for (int mi = 0; mi < 2; mi++) {
                MMA_BF16(acc[mi][nj], ah[mi][0], ah[mi][1], ah[mi][2], ah[mi][3], b.x, b.y);
                MMA_BF16(acc[mi][nj], al[mi][0], al[mi][1], al[mi][2], al[mi][3], b.x, b.y);
                MMA_BF16(acc[mi][nj], ah[mi][0], ah[mi][1], ah[mi][2], ah[mi][3], b.z, b.w);
                MMA_BF16(acc[mi][nj], al[mi][0], al[mi][1], al[mi][2], al[mi][3], b.z, b.w);
            }
        }
        pah += 8; pal += 8; wp += 32;
    }
    #pragma unroll
    for (int mi = 0; mi < 2; mi++)
        #pragma unroll
        for (int nj = 0; nj < 4; nj++) {
            int col = n0 + nj * 8 + c2;
            *reinterpret_cast<float2*>(C + (mi * 16 + r) * ldc + col) =
                make_float2(acc[mi][nj][0], acc[mi][nj][1]);
            *reinterpret_cast<float2*>(C + (mi * 16 + 8 + r) * ldc + col) =
                make_float2(acc[mi][nj][2], acc[mi][nj][3]);
        }
}

// embpre: [2048,2048] = emb @ Wih0[:, :512]^T
__global__ __launch_bounds__(256)
void embpre_mma_kernel() {
    int g = blockIdx.x * 8 + (threadIdx.x >> 5);
    int lane = threadIdx.x & 31;
    int rb = g >> 6;
    int nt = g & 63;
    mma_row32(g_embH + rb * 32 * 512, g_embL + rb * 32 * 512,
              g_pkIH0, nt * 4, 0, 32,
              g_embpre + (long long)rb * 32 * 2048, 2048, nt * 32, lane);
}

// encproj: [2048,512] = enc_flat @ W_a (via W_a^T pack)
__global__ __launch_bounds__(256)
void encproj_mma_kernel() {
    int g = blockIdx.x * 8 + (threadIdx.x >> 5);   // 0..1023
    int lane = threadIdx.x & 31;
    int rb = g >> 4;        // 64 row blocks
    int nt = g & 15;        // 16 n32 tiles
    mma_row32(g_encH + rb * 32 * 512, g_encL + rb * 32 * 512,
              g_pkWaT, nt * 4, 0, 32,
              g_encproj + (long long)rb * 32 * 512, 512, nt * 32, lane);
}

// ---------------- persistent recurrence (5 barriers/step) ----------------
__device__ __forceinline__ float sigmf(float x) { return 1.f / (1.f + expf(-x)); }

__global__ __launch_bounds__(256, 1)
void decoder_persistent(const float* __restrict__ enc,
                        const float* __restrict__ b_ih0,
                        const float* __restrict__ b_hh0,
                        const float* __restrict__ b_ih1,
                        const float* __restrict__ b_hh1) {
    __shared__ float h1s[512];
    __shared__ float sc[64];
    __shared__ float s_red[2];

    const int cta = blockIdx.x;
    const int tid = threadIdx.x;
    const int lane = tid & 31;
    const int wid = tid >> 5;
    unsigned bar_t = 0;

    auto gbar = [&]() {
        __syncthreads();
        __threadfence();
        bar_t += NCTA;
        if (tid == 0) {
            atomicAdd(&g_barcnt, 1u);
            while (*(volatile unsigned*)&g_barcnt < bar_t) { }
        }
        __syncthreads();
    };

    for (int t = 0; t < TT; t++) {
        float* feat_t = g_feat + t * 32768;
        const float* ep = g_embpre + (long long)t * 65536;

        // ==== Phase A: attention (CTA 0-31) || g0hh, g1hh GEMMs (CTA 32-143)
        if (cta < 32) {
            const int b = cta;
            #pragma unroll
            for (int r = 0; r < 2; r++) {
                int k = tid + r * 256;
                h1s[k] = __ldcg(g_h + 16384 + b * 512 + k);
            }
            __syncthreads();
            // scores from precomputed encproj
            const float* epj = g_encproj + (long long)b * 64 * 512;
            #pragma unroll
            for (int si = 0; si < 8; si++) {
                int s = wid * 8 + si;
                const float* row = epj + s * 512;
                float sum = 0.f;
                for (int j = lane; j < 512; j += 32) sum += row[j] * h1s[j];
                #pragma unroll
                for (int o = 16; o; o >>= 1) sum += __shfl_down_sync(0xffffffffu, sum, o);
                if (lane == 0) sc[s] = sum;
            }
            __syncthreads();
            if (tid == 0) {
                float mx = sc[0];
                for (int s = 1; s < 64; s++) mx = fmaxf(mx, sc[s]);
                s_red[0] = mx;
            }
            __syncthreads();
            if (tid < 64) sc[tid] = expf(sc[tid] - s_red[0]);
            __syncthreads();
            if (tid == 0) {
                float sm = 0.f;
                for (int s = 0; s < 64; s++) sm += sc[s];
                s_red[1] = 1.f / sm;
            }
            __syncthreads();
            const float inv = s_red[1];
            const float* encb = enc + (long long)b * SS * 512;
            for (int k = tid; k < 512; k += 256) {
                float acc = 0.f;
                #pragma unroll 8
                for (int s = 0; s < 64; s++) acc += sc[s] * encb[s * 512 + k];
                float cv = acc * inv;
                feat_t[b * 1024 + 512 + k] = cv;
                unsigned short hi = bf16hi(cv);
                unsigned short lo = bf16hi(cv - __bfloat162float(__ushort_as_bfloat16(hi)));
                g_ctxH[b * 512 + k] = hi;
                g_ctxL[b * 512 + k] = lo;
            }
        } else {
            int g2 = (cta - 32) * 8 + wid;         // 0..895
            if (g2 < 256) {
                int nt_ = g2 >> 2, ks = g2 & 3;
                mma_row32(g_h0H, g_h0L, g_pkHH0, nt_ * 4, ks * 8, 8,
                          g_g0hh + ks * 65536, 2048, nt_ * 32, lane);
            } else if (g2 < 512) {
                int g3 = g2 - 256;
                int nt_ = g3 >> 2, ks = g3 & 3;
                mma_row32(g_h1H, g_h1L, g_pkHH1, nt_ * 4, ks * 8, 8,
                          g_g1hh + ks * 65536, 2048, nt_ * 32, lane);
            }
        }
        gbar();

        // ==== Phase B: g0ctx = ctx @ Wihc^T (512 warps, ksplit 8) ====
        {
            int g = cta * 8 + wid;
            if (g < 512) {
                int nt_ = g >> 3, ks = g & 7;
                mma_row32(g_ctxH, g_ctxL, g_pkIHC, nt_ * 4, ks * 4, 4,
                          g_g0ctx + ks * 65536, 2048, nt_ * 32, lane);
            }
        }
        gbar();

        // ==== Phase C: LSTM0 update ====
        {
            int idx = cta * 256 + tid;
            if (idx < 16384) {
                int b = idx >> 9, u = idx & 511;
                int gg0 = b * 2048 + u;
                float gv[4];
                #pragma unroll
                for (int q = 0; q < 4; q++) {
                    int o = gg0 + q * 512;
                    float v = ep[o];
                    #pragma unroll
                    for (int s = 0; s < 4; s++) v += __ldcg(g_g0hh + s * 65536 + o);
                    #pragma unroll
                    for (int s = 0; s < 8; s++) v += __ldcg(g_g0ctx + s * 65536 + o);
                    gv[q] = v + __ldg(b_ih0 + q * 512 + u) + __ldg(b_hh0 + q * 512 + u);
                }
                float cv = g_c[idx];
                float cn = sigmf(gv[1]) * cv + sigmf(gv[0]) * tanhf(gv[2]);
                float hn = sigmf(gv[3]) * tanhf(cn);
                g_c[idx] = cn;
                g_h[idx] = hn;
                unsigned short hi = bf16hi(hn);
                unsigned short lo = bf16hi(hn - __bfloat162float(__ushort_as_bfloat16(hi)));
                g_h0H[idx] = hi;
                g_h0L[idx] = lo;
            }
        }
        gbar();

        // ==== Phase D: g1ih = h0 @ Wih1^T (512 warps, ksplit 8) ====
        {
            int g = cta * 8 + wid;
            if (g < 512) {
                int nt_ = g >> 3, ks = g & 7;
                mma_row32(g_h0H, g_h0L, g_pkIH1, nt_ * 4, ks * 4, 4,
                          g_g1ih + ks * 65536, 2048, nt_ * 32, lane);
            }
        }
        gbar();

        // ==== Phase E: LSTM1 update + feat write ====
        {
            int idx = cta * 256 + tid;
            if (idx < 16384) {
                int b = idx >> 9, u = idx & 511;
                int gg0 = b * 2048 + u;
                float gv[4];
                #pragma unroll
                for (int q = 0; q < 4; q++) {
                    int o = gg0 + q * 512;
                    float v = 0.f;
                    #pragma unroll
                    for (int s = 0; s < 4; s++) v += __ldcg(g_g1hh + s * 65536 + o);
                    #pragma unroll
                    for (int s = 0; s < 8; s++) v += __ldcg(g_g1ih + s * 65536 + o);
                    gv[q] = v + __ldg(b_ih1 + q * 512 + u) + __ldg(b_hh1 + q * 512 + u);
                }
                float cv = g_c[16384 + idx];
                float cn = sigmf(gv[1]) * cv + sigmf(gv[0]) * tanhf(gv[2]);
                float hn = sigmf(gv[3]) * tanhf(cn);
                g_c[16384 + idx] = cn;
                g_h[16384 + idx] = hn;
                feat_t[b * 1024 + u] = hn;
                unsigned short hi = bf16hi(hn);
                unsigned short lo = bf16hi(hn - __bfloat162float(__ushort_as_bfloat16(hi)));
                g_h1H[idx] = hi;
                g_h1L[idx] = lo;
            }
        }
        gbar();
    }
}

// ---------------- big projection GEMM (3-term, unchanged) ----------------
#define GK 1024
#define KC 32
#define NKC (GK / KC)
#define RST 40
#define BUF_BF16 (128 * RST)
#define STAGE_BF16 (4 * BUF_BF16)
#define GEMM_SMEM (2 * STAGE_BF16 * 2)

__global__ __launch_bounds__(256, 1)
void big_gemm_mma(const __nv_bfloat16* __restrict__ AH, const __nv_bfloat16* __restrict__ AL,
                  const __nv_bfloat16* __restrict__ BH, const __nv_bfloat16* __restrict__ BL,
                  const float* __restrict__ bias, float* __restrict__ out) {
    extern __shared__ __nv_bfloat16 sm[];
    const int tid = threadIdx.x;
    const int lane = tid & 31;
    const int wid = tid >> 5;
    const int wm = wid >> 1;
    const int wn = wid & 1;
    const int m0 = blockIdx.x * 128;
    const int n0 = blockIdx.y * 128;
    const uint32_t smem_base = smem_to_u32(sm);

    float acc[2][8][4];
    #pragma unroll
    for (int i = 0; i < 2; i++)
        #pragma unroll
        for (int j = 0; j < 8; j++)
            #pragma unroll
            for (int v = 0; v < 4; v++) acc[i][j][v] = 0.f;

    auto load_stage = [&](int st, int kc) {
        const uint32_t sb = smem_base + st * STAGE_BF16 * 2;
        const int k0 = kc * KC;
        #pragma unroll
        for (int r = 0; r < 2; r++) {
            int idx = tid + r * 256;
            int row = idx >> 2, c = idx & 3;
            uint32_t doff = (uint32_t)(row * RST + c * 8) * 2;
            long long aoff = (long long)(m0 + row) * GK + k0 + c * 8;
            long long boff = (long long)(n0 + row) * GK + k0 + c * 8;
            CP16(sb + doff,                AH + aoff);
            CP16(sb + BUF_BF16 * 2 + doff, AL + aoff);
            CP16(sb + BUF_BF16 * 4 + doff, BH + boff);
            CP16(sb + BUF_BF16 * 6 + doff, BL + boff);
        }
        CP_COMMIT();
    };

    load_stage(0, 0);

    for (int kc = 0; kc < NKC; kc++) {
        const int st = kc & 1;
        if (kc + 1 < NKC) { load_stage(st ^ 1, kc + 1); CP_WAIT1(); }
        else              { CP_WAIT0(); }
        __syncthreads();

        const uint32_t sb = smem_base + st * STAGE_BF16 * 2;
        uint32_t ah[2][2][4], al[2][2][4];
        #pragma unroll
        for (int i = 0; i < 2; i++)
            #pragma unroll
            for (int kk = 0; kk < 2; kk++) {
                uint32_t addr = sb + (uint32_t)((wm * 32 + i * 16 + (lane & 15)) * RST
                                                + kk * 16 + (lane >> 4) * 8) * 2;
                LDSM_X4(ah[i][kk][0], ah[i][kk][1], ah[i][kk][2], ah[i][kk][3], addr);
                LDSM_X4(al[i][kk][0], al[i][kk][1], al[i][kk][2], al[i][kk][3],
                        addr + BUF_BF16 * 2);
            }
        #pragma unroll
        for (int j = 0; j < 8; j++) {
            #pragma unroll
            for (int kk = 0; kk < 2; kk++) {
                uint32_t baddr = sb + BUF_BF16 * 4
                    + (uint32_t)((wn * 64 + j * 8 + (lane & 7)) * RST
                                 + kk * 16 + ((lane >> 3) & 1) * 8) * 2;
                uint32_t bh0, bh1, bl0, bl1;
                LDSM_X2(bh0, bh1, baddr);
                LDSM_X2(bl0, bl1, baddr + BUF_BF16 * 2);
                #pragma unroll
                for (int i = 0; i < 2; i++) {
                    MMA_BF16(acc[i][j], ah[i][kk][0], ah[i][kk][1], ah[i][kk][2], ah[i][kk][3], bh0, bh1);
                    MMA_BF16(acc[i][j], al[i][kk][0], al[i][kk][1], al[i][kk][2], al[i][kk][3], bh0, bh1);
                    MMA_BF16(acc[i][j], ah[i][kk][0], ah[i][kk][1], ah[i][kk][2], ah[i][kk][3], bl0, bl1);
                }
            }
        }
        __syncthreads();
    }

    #pragma unroll
    for (int i = 0; i < 2; i++) {
        int mA = m0 + wm * 32 + i * 16 + (lane >> 2);
        int mB = mA + 8;
        int tA = mA >> 5, bA = mA & 31;
        int tB = mB >> 5, bB = mB & 31;
        float* rowA = out + (long long)((bA << 6) + tA) * VV;
        float* rowB = out + (long long)((bB << 6) + tB) * VV;
        #pragma unroll
        for (int j = 0; j < 8; j++) {
            int n = n0 + wn * 64 + j * 8 + (lane & 3) * 2;
            float bv0 = bias[n], bv1 = bias[n + 1];
            float2 vA = make_float2(acc[i][j][0] + bv0, acc[i][j][1] + bv1);
            float2 vB = make_float2(acc[i][j][2] + bv0, acc[i][j][3] + bv1);
            *reinterpret_cast<float2*>(rowA + n) = vA;
            *reinterpret_cast<float2*>(rowB + n) = vB;
        }
    }
}

// ---------------- host launcher ----------------
extern "C" void kernel_launch(void* const* d_in, const int* in_sizes, int n_in,
                              void* d_out, int out_size) {
    const int*   tgt    = (const int*)  d_in[0];
    const float* enc    = (const float*)d_in[1];
    const float* hidden = (const float*)d_in[2];
    const float* cell   = (const float*)d_in[3];
    const float* emb    = (const float*)d_in[4];
    const float* W_a    = (const float*)d_in[5];
    const float* W_ih0  = (const float*)d_in[6];
    const float* W_hh0  = (const float*)d_in[7];
    const float* b_ih0  = (const float*)d_in[8];
    const float* b_hh0  = (const float*)d_in[9];
    const float* W_ih1  = (const float*)d_in[10];
    const float* W_hh1  = (const float*)d_in[11];
    const float* b_ih1  = (const float*)d_in[12];
    const float* b_hh1  = (const float*)d_in[13];
    const float* W_out  = (const float*)d_in[14];
    const float* b_out  = (const float*)d_in[15];
    float* out = (float*)d_out;

    float *p_feat;
    __nv_bfloat16 *p_WH, *p_WL, *p_fH, *p_fL, *p_encH, *p_encL;
    uint4 *pkWaT, *pkHH0, *pkHH1, *pkIH1, *pkIHC, *pkIH0;
    cudaGetSymbolAddress((void**)&p_feat, g_feat);
    cudaGetSymbolAddress((void**)&p_WH,   g_WH);
    cudaGetSymbolAddress((void**)&p_WL,   g_WL);
    cudaGetSymbolAddress((void**)&p_fH,   g_fH);
    cudaGetSymbolAddress((void**)&p_fL,   g_fL);
    cudaGetSymbolAddress((void**)&p_encH, g_encH);
    cudaGetSymbolAddress((void**)&p_encL, g_encL);
    cudaGetSymbolAddress((void**)&pkWaT,  g_pkWaT);
    cudaGetSymbolAddress((void**)&pkHH0,  g_pkHH0);
    cudaGetSymbolAddress((void**)&pkHH1,  g_pkHH1);
    cudaGetSymbolAddress((void**)&pkIH1,  g_pkIH1);
    cudaGetSymbolAddress((void**)&pkIHC,  g_pkIHC);
    cudaGetSymbolAddress((void**)&pkIH0,  g_pkIH0);

    init_state_kernel<<<64, 512>>>(hidden, cell);
    embed_kernel<<<BATCH * TT, 128>>>(tgt, emb);

    // split enc into bf16 duals (for encproj GEMM)
    split_bf16_kernel<<<1024, 256>>>((const float4*)enc, (uint2*)p_encH, (uint2*)p_encL,
                                     2048 * 512 / 4);

    // pack weights
    pack_t_kernel<<<64, 1024>>>(W_a,         512,  pkWaT);
    pack_kernel<<<256, 1024>>>(W_hh0,        512,  pkHH0);
    pack_kernel<<<256, 1024>>>(W_hh1,        512,  pkHH1);
    pack_kernel<<<256, 1024>>>(W_ih1,        512,  pkIH1);
    pack_kernel<<<256, 1024>>>(W_ih0 + 512,  1024, pkIHC);
    pack_kernel<<<256, 1024>>>(W_ih0,        1024, pkIH0);

    // precompute emb @ Wih0[:, :512]^T and enc @ W_a
    embpre_mma_kernel<<<512, 256>>>();
    encproj_mma_kernel<<<128, 256>>>();

    // fused persistent recurrence
    decoder_persistent<<<NCTA, 256>>>(enc, b_ih0, b_hh0, b_ih1, b_hh1);

    // split W_out and feat for big GEMM
    split_bf16_kernel<<<4096, 256>>>((const float4*)W_out, (uint2*)p_WH, (uint2*)p_WL,
                                     VV * 1024 / 4);
    split_bf16_kernel<<<2048, 256>>>((const float4*)p_feat, (uint2*)p_fH, (uint2*)p_fL,
                                     2048 * 1024 / 4);

    // tensor-core projection
    cudaFuncSetAttribute(big_gemm_mma, cudaFuncAttributeMaxDynamicSharedMemorySize, GEMM_SMEM);
    big_gemm_mma<<<dim3(16, VV / 128), 256, GEMM_SMEM>>>(p_fH, p_fL, p_WH, p_WL, b_out, out);

    tail_copy_kernel<<<64, 512>>>(out);
}